// round 4
// baseline (speedup 1.0000x reference)
#include <cuda_runtime.h>
#include <math.h>

#define BDIM 4096
#define DDIM 1024
#define NDOM 8
#define TILE 64
#define NTILE (BDIM / TILE)   // 64

// Scratch (no allocations allowed): row squared norms + per-domain accumulators.
__device__ float g_sq[BDIM];
__device__ float g_domsum[NDOM];

// ---------------------------------------------------------------------------
// Kernel 1: per-row squared norms via low-error tree reduction (mimics XLA's
// small-error reduce; error ~1e-4 scale, negligible vs the sequential matmul
// error that dominates the diagonal residual). Also zero-inits accumulators.
// ---------------------------------------------------------------------------
__global__ void __launch_bounds__(256) sqnorm_kernel(const float* __restrict__ f) {
    int row = blockIdx.x;
    const float4* fr = (const float4*)(f + (size_t)row * DDIM);
    float4 v = fr[threadIdx.x];
    float s = v.x * v.x + v.y * v.y + v.z * v.z + v.w * v.w;

    __shared__ float red[8];
    #pragma unroll
    for (int o = 16; o > 0; o >>= 1) s += __shfl_xor_sync(0xffffffffu, s, o);
    if ((threadIdx.x & 31) == 0) red[threadIdx.x >> 5] = s;
    __syncthreads();
    if (threadIdx.x == 0) {
        float t = 0.f;
        #pragma unroll
        for (int w = 0; w < 8; w++) t += red[w];
        g_sq[row] = t;
    }
    if (row == 0 && threadIdx.x < NDOM) g_domsum[threadIdx.x] = 0.f;
}

// ---------------------------------------------------------------------------
// Kernel 2: diagonal contribution. dist(i,i) in the reference is
// sqrt(2*(sq_i - dot_ii)) where dot_ii comes from cublas SGEMM: a SINGLE
// accumulator, strictly sequential FMA over k=0..1023 in natural order.
// We replicate exactly that accumulation structure so the rounding-residual
// distribution (sigma_r ~ 8.5e-4) matches the reference's (8.8e-4 inferred
// from the round-1 measurement). The fmaf chain is a serial dependence so
// the compiler cannot reassociate it, fast-math or not.
// ---------------------------------------------------------------------------
__global__ void __launch_bounds__(128) diag_kernel(const float* __restrict__ f,
                                                   const int* __restrict__ lab) {
    int row = blockIdx.x * 128 + threadIdx.x;
    const float4* fr = (const float4*)(f + (size_t)row * DDIM);
    float acc = 0.f;
    for (int k = 0; k < DDIM / 4; k++) {
        float4 v = fr[k];
        acc = fmaf(v.x, v.x, acc);
        acc = fmaf(v.y, v.y, acc);
        acc = fmaf(v.z, v.z, acc);
        acc = fmaf(v.w, v.w, acc);
    }
    float r = 2.0f * (g_sq[row] - acc);       // residual d2 on the diagonal
    float dist = (r > 0.f) ? sqrtf(r) : 0.f;  // matches where(d2>0, sqrt, 0)
    float val = 1.0f - dist;                  // MARGIN - dist
    if (val > 0.f) atomicAdd(&g_domsum[lab[row]], val);
}

// ---------------------------------------------------------------------------
// Kernel 3: fused triangular Gram-matrix + hinge + per-domain accumulation.
// Off-diagonal d2 ~ 2048 >> margin^2 = 1 (min over all pairs ~1700), so the
// d2 < 1 test essentially never fires; nonzero adds are rare -> atomics cheap.
// Strict lower triangle only (i > j), x2 weight; diagonal handled above.
// ---------------------------------------------------------------------------
__global__ void __launch_bounds__(256) fused_gemm_kernel(const float* __restrict__ f,
                                                         const int* __restrict__ lab) {
    __shared__ float As[TILE][17];
    __shared__ float Bs[TILE][17];

    // linear block id -> (bi, bj) with bi >= bj
    int bid = blockIdx.x;
    int bi = (int)((sqrtf(8.0f * (float)bid + 1.0f) - 1.0f) * 0.5f);
    while ((bi + 1) * (bi + 2) / 2 <= bid) ++bi;
    while (bi * (bi + 1) / 2 > bid) --bi;
    int bj = bid - bi * (bi + 1) / 2;

    int tx = threadIdx.x & 15;
    int ty = threadIdx.x >> 4;

    float c[4][4];
    #pragma unroll
    for (int qa = 0; qa < 4; qa++)
        #pragma unroll
        for (int qb = 0; qb < 4; qb++) c[qa][qb] = 0.f;

    int rowA = bi * TILE;
    int rowB = bj * TILE;

    int lr = threadIdx.x >> 2;        // 0..63: row within tile
    int lc = (threadIdx.x & 3) * 4;   // 0,4,8,12: k offset

    for (int kc = 0; kc < DDIM; kc += 16) {
        float4 va = *(const float4*)(f + (size_t)(rowA + lr) * DDIM + kc + lc);
        float4 vb = *(const float4*)(f + (size_t)(rowB + lr) * DDIM + kc + lc);
        __syncthreads();
        As[lr][lc + 0] = va.x; As[lr][lc + 1] = va.y;
        As[lr][lc + 2] = va.z; As[lr][lc + 3] = va.w;
        Bs[lr][lc + 0] = vb.x; Bs[lr][lc + 1] = vb.y;
        Bs[lr][lc + 2] = vb.z; Bs[lr][lc + 3] = vb.w;
        __syncthreads();

        #pragma unroll
        for (int kk = 0; kk < 16; kk++) {
            float a[4], b[4];
            #pragma unroll
            for (int q = 0; q < 4; q++) a[q] = As[ty + 16 * q][kk];
            #pragma unroll
            for (int q = 0; q < 4; q++) b[q] = Bs[tx + 16 * q][kk];
            #pragma unroll
            for (int qa = 0; qa < 4; qa++)
                #pragma unroll
                for (int qb = 0; qb < 4; qb++)
                    c[qa][qb] += a[qa] * b[qb];
        }
    }

    // Epilogue: hinge + domain-matched accumulation (strict lower triangle, x2).
    #pragma unroll
    for (int qa = 0; qa < 4; qa++) {
        int i = rowA + ty + 16 * qa;
        float sqi = g_sq[i];
        int li = lab[i];
        #pragma unroll
        for (int qb = 0; qb < 4; qb++) {
            int j = rowB + tx + 16 * qb;
            if (j >= i) continue;  // strict lower triangle; diag handled elsewhere
            float d2 = sqi + g_sq[j] - 2.0f * c[qa][qb];
            if (d2 < 1.0f) {
                if (li == lab[j]) {
                    float dist = (d2 > 0.f) ? sqrtf(d2) : 0.f;
                    float val = 1.0f - dist;
                    if (val > 0.f) atomicAdd(&g_domsum[li], 2.0f * val);
                }
            }
        }
    }
}

// ---------------------------------------------------------------------------
// Kernel 4: histogram labels, divide per-domain sums, average valid domains.
// ---------------------------------------------------------------------------
__global__ void __launch_bounds__(256) finalize_kernel(const int* __restrict__ lab,
                                                       float* __restrict__ out) {
    __shared__ int hist[NDOM];
    if (threadIdx.x < NDOM) hist[threadIdx.x] = 0;
    __syncthreads();
    for (int i = threadIdx.x; i < BDIM; i += 256)
        atomicAdd(&hist[lab[i]], 1);
    __syncthreads();
    if (threadIdx.x == 0) {
        float acc = 0.f, cnt = 0.f;
        for (int d = 0; d < NDOM; d++) {
            int n = hist[d];
            if (n > 1) {
                acc += g_domsum[d] / (float)(n * n);
                cnt += 1.f;
            }
        }
        *out = (cnt > 0.f) ? (acc / cnt) : 0.f;
    }
}

extern "C" void kernel_launch(void* const* d_in, const int* in_sizes, int n_in,
                              void* d_out, int out_size) {
    const float* f   = (const float*)d_in[0];
    const int*   lab = (const int*)d_in[1];
    (void)in_sizes; (void)n_in; (void)out_size;

    sqnorm_kernel<<<BDIM, 256>>>(f);
    diag_kernel<<<BDIM / 128, 128>>>(f, lab);
    int nblocks = NTILE * (NTILE + 1) / 2;   // 2080 triangular tiles
    fused_gemm_kernel<<<nblocks, 256>>>(f, lab);
    finalize_kernel<<<1, 256>>>(lab, (float*)d_out);
}

// round 5
// speedup vs baseline: 8.1121x; 8.1121x over previous
#include <cuda_runtime.h>
#include <math.h>

#define BDIM 4096
#define DDIM 1024
#define NDOM 8
#define KSCR 64                 // screening dims (lower-bound on d^2)
#define TILE 64
#define NTILE (BDIM / TILE)     // 64
#define SCREEN_THRESH 16.0f     // partial-d2 mean=128, sigma=22.6 -> z=-4.96

// Scratch (no allocations allowed).
__device__ float g_sq[BDIM];    // full squared norms (tree reduce)
__device__ float g_p[BDIM];     // partial squared norms over first KSCR dims
__device__ float g_domsum[NDOM];

// ---------------------------------------------------------------------------
// Kernel 1: per-row full squared norm (tree reduce, mimics XLA reduce whose
// error is negligible) + partial squared norm over the first KSCR dims.
// Also zero-inits the per-domain accumulators.
// ---------------------------------------------------------------------------
__global__ void __launch_bounds__(256) sqnorm_kernel(const float* __restrict__ f) {
    int row = blockIdx.x;
    const float4* fr = (const float4*)(f + (size_t)row * DDIM);
    float4 v = fr[threadIdx.x];
    float s = v.x * v.x + v.y * v.y + v.z * v.z + v.w * v.w;
    // first KSCR floats = float4 indices 0..15 (threads 0..15)
    float sp = (threadIdx.x < KSCR / 4) ? s : 0.f;

    __shared__ float red[8];
    float st = s;
    #pragma unroll
    for (int o = 16; o > 0; o >>= 1) st += __shfl_xor_sync(0xffffffffu, st, o);
    #pragma unroll
    for (int o = 16; o > 0; o >>= 1) sp += __shfl_xor_sync(0xffffffffu, sp, o);
    if ((threadIdx.x & 31) == 0) red[threadIdx.x >> 5] = st;
    __syncthreads();
    if (threadIdx.x == 0) {
        float t = 0.f;
        #pragma unroll
        for (int w = 0; w < 8; w++) t += red[w];
        g_sq[row] = t;
        g_p[row] = sp;   // warp 0 holds the full partial sum
    }
    if (row == 0 && threadIdx.x < NDOM) g_domsum[threadIdx.x] = 0.f;
}

// ---------------------------------------------------------------------------
// Kernel 2: diagonal contribution. dist(i,i) in the reference is
// sqrt(2*(sq_i - dot_ii)) where dot_ii comes from cublas SGEMM: a SINGLE
// accumulator, strictly sequential FMA over k in natural order. The fmaf
// chain is serially dependent, so the compiler cannot reassociate it.
// This path produces the ENTIRE loss value (sigma_r ~ 8.5e-4 residuals).
// ---------------------------------------------------------------------------
__global__ void __launch_bounds__(128) diag_kernel(const float* __restrict__ f,
                                                   const int* __restrict__ lab) {
    int row = blockIdx.x * 128 + threadIdx.x;
    const float4* fr = (const float4*)(f + (size_t)row * DDIM);
    float acc = 0.f;
    for (int k = 0; k < DDIM / 4; k++) {
        float4 v = fr[k];
        acc = fmaf(v.x, v.x, acc);
        acc = fmaf(v.y, v.y, acc);
        acc = fmaf(v.z, v.z, acc);
        acc = fmaf(v.w, v.w, acc);
    }
    float r = 2.0f * (g_sq[row] - acc);       // residual d2 on the diagonal
    float dist = (r > 0.f) ? sqrtf(r) : 0.f;  // matches where(d2>0, sqrt, 0)
    float val = 1.0f - dist;                  // MARGIN - dist
    if (val > 0.f) atomicAdd(&g_domsum[lab[row]], val);
}

// ---------------------------------------------------------------------------
// Exact fallback for screened-in pairs: reference-order (cublas-like)
// sequential dot, then the reference hinge. Expected call count ~0-3 total.
// ---------------------------------------------------------------------------
__device__ float pair_val_exact(const float* __restrict__ f, int i, int j) {
    const float4* a = (const float4*)(f + (size_t)i * DDIM);
    const float4* b = (const float4*)(f + (size_t)j * DDIM);
    float acc = 0.f;
    for (int k = 0; k < DDIM / 4; k++) {
        float4 va = a[k], vb = b[k];
        acc = fmaf(va.x, vb.x, acc);
        acc = fmaf(va.y, vb.y, acc);
        acc = fmaf(va.z, vb.z, acc);
        acc = fmaf(va.w, vb.w, acc);
    }
    float d2 = g_sq[i] + g_sq[j] - 2.0f * acc;
    float dist = (d2 > 0.f) ? sqrtf(d2) : 0.f;
    return 1.0f - dist;
}

// ---------------------------------------------------------------------------
// Kernel 3: K=64 screening Gram over the strict lower triangle.
// partial_d2(i,j) = p_i + p_j - 2*dot64(i,j) is a LOWER BOUND on d2(i,j)
// (sum of squares over remaining 960 dims is >= 0). If the bound exceeds
// SCREEN_THRESH (margin^2 = 1 plus a >5-sigma statistical + fp32 cushion),
// the pair's hinge is provably zero. Survivors get an exact recheck.
// Single smem stage: full 64x64x64 tiles resident (33 KB).
// ---------------------------------------------------------------------------
__global__ void __launch_bounds__(256) screen_kernel(const float* __restrict__ f,
                                                     const int* __restrict__ lab) {
    __shared__ float As[TILE][KSCR + 1];
    __shared__ float Bs[TILE][KSCR + 1];

    // linear block id -> (bi, bj) with bi >= bj
    int bid = blockIdx.x;
    int bi = (int)((sqrtf(8.0f * (float)bid + 1.0f) - 1.0f) * 0.5f);
    while ((bi + 1) * (bi + 2) / 2 <= bid) ++bi;
    while (bi * (bi + 1) / 2 > bid) --bi;
    int bj = bid - bi * (bi + 1) / 2;

    int rowA = bi * TILE;
    int rowB = bj * TILE;

    // Cooperative load: 256 threads x 4 float4 = 64 rows x 64 floats per tile.
    int lr = threadIdx.x >> 2;          // 0..63
    int lc4 = (threadIdx.x & 3) * 4;    // float4 index base: 0,4,8,12
    {
        const float4* fa = (const float4*)(f + (size_t)(rowA + lr) * DDIM) + lc4;
        const float4* fb = (const float4*)(f + (size_t)(rowB + lr) * DDIM) + lc4;
        #pragma unroll
        for (int q = 0; q < 4; q++) {
            float4 va = fa[q];
            float4 vb = fb[q];
            int c = (lc4 + q) * 4;
            As[lr][c + 0] = va.x; As[lr][c + 1] = va.y;
            As[lr][c + 2] = va.z; As[lr][c + 3] = va.w;
            Bs[lr][c + 0] = vb.x; Bs[lr][c + 1] = vb.y;
            Bs[lr][c + 2] = vb.z; Bs[lr][c + 3] = vb.w;
        }
    }
    __syncthreads();

    int tx = threadIdx.x & 15;
    int ty = threadIdx.x >> 4;

    float c[4][4];
    #pragma unroll
    for (int qa = 0; qa < 4; qa++)
        #pragma unroll
        for (int qb = 0; qb < 4; qb++) c[qa][qb] = 0.f;

    #pragma unroll 8
    for (int kk = 0; kk < KSCR; kk++) {
        float a[4], b[4];
        #pragma unroll
        for (int q = 0; q < 4; q++) a[q] = As[ty + 16 * q][kk];
        #pragma unroll
        for (int q = 0; q < 4; q++) b[q] = Bs[tx + 16 * q][kk];
        #pragma unroll
        for (int qa = 0; qa < 4; qa++)
            #pragma unroll
            for (int qb = 0; qb < 4; qb++)
                c[qa][qb] += a[qa] * b[qb];
    }

    // Epilogue: lower-bound test; rare survivors -> exact recheck.
    #pragma unroll
    for (int qa = 0; qa < 4; qa++) {
        int i = rowA + ty + 16 * qa;
        float pi = g_p[i];
        #pragma unroll
        for (int qb = 0; qb < 4; qb++) {
            int j = rowB + tx + 16 * qb;
            if (j >= i) continue;    // strict lower triangle; diag handled above
            float d2p = pi + g_p[j] - 2.0f * c[qa][qb];
            if (d2p < SCREEN_THRESH) {
                if (lab[i] == lab[j]) {
                    float val = pair_val_exact(f, i, j);
                    if (val > 0.f) atomicAdd(&g_domsum[lab[i]], 2.0f * val);
                }
            }
        }
    }
}

// ---------------------------------------------------------------------------
// Kernel 4: histogram labels, divide per-domain sums, average valid domains.
// ---------------------------------------------------------------------------
__global__ void __launch_bounds__(256) finalize_kernel(const int* __restrict__ lab,
                                                       float* __restrict__ out) {
    __shared__ int hist[NDOM];
    if (threadIdx.x < NDOM) hist[threadIdx.x] = 0;
    __syncthreads();
    for (int i = threadIdx.x; i < BDIM; i += 256)
        atomicAdd(&hist[lab[i]], 1);
    __syncthreads();
    if (threadIdx.x == 0) {
        float acc = 0.f, cnt = 0.f;
        for (int d = 0; d < NDOM; d++) {
            int n = hist[d];
            if (n > 1) {
                acc += g_domsum[d] / (float)(n * n);
                cnt += 1.f;
            }
        }
        *out = (cnt > 0.f) ? (acc / cnt) : 0.f;
    }
}

extern "C" void kernel_launch(void* const* d_in, const int* in_sizes, int n_in,
                              void* d_out, int out_size) {
    const float* f   = (const float*)d_in[0];
    const int*   lab = (const int*)d_in[1];
    (void)in_sizes; (void)n_in; (void)out_size;

    sqnorm_kernel<<<BDIM, 256>>>(f);
    diag_kernel<<<BDIM / 128, 128>>>(f, lab);
    int nblocks = NTILE * (NTILE + 1) / 2;   // 2080 triangular tiles
    screen_kernel<<<nblocks, 256>>>(f, lab);
    finalize_kernel<<<1, 256>>>(lab, (float*)d_out);
}

// round 7
// speedup vs baseline: 17.4424x; 2.1502x over previous
#include <cuda_runtime.h>
#include <math.h>

#define BDIM 4096
#define DDIM 1024
#define NDOM 8
#define KSCR 32                 // screening dims (rigorous lower bound on d^2)
#define TILE 64
#define MAXNT 16                // supports bucket sizes up to 1024 (mean 512, sd 21)
#define MAXTRI (MAXNT * (MAXNT + 1) / 2)   // 136 tri-tiles per domain
#define SCREEN_THRESH 4.0f      // partial-d2 over 32 dims: mean 64, sigma 16 -> z=-3.75

// Scratch (no allocations allowed). All zero at module load; the screen
// kernel's finalizer resets g_domsum/g_arrive to zero at the end of every
// run so graph replays are deterministic.
__device__ float g_sq[BDIM];          // full squared norms (tree reduce)
__device__ float g_p[BDIM];           // partial squared norms over first KSCR dims
__device__ int   g_idx[NDOM][BDIM];   // per-domain compacted row indices
__device__ int   g_cnt[NDOM];         // per-domain counts
__device__ float g_domsum[NDOM];      // per-domain hinge sums
__device__ unsigned int g_arrive;     // completion counter for fused finalize

// ---------------------------------------------------------------------------
// Kernel 1: blocks 0..BDIM-1: per-row full squared norm (tree reduce) and
// partial norm over the first KSCR dims. Block BDIM: deterministic
// warp-ballot bucketing of rows by domain (warp w owns domain w).
// ---------------------------------------------------------------------------
__global__ void __launch_bounds__(256) sqnorm_bucket_kernel(const float* __restrict__ f,
                                                            const int* __restrict__ lab) {
    if (blockIdx.x < BDIM) {
        int row = blockIdx.x;
        const float4* fr = (const float4*)(f + (size_t)row * DDIM);
        float4 v = fr[threadIdx.x];
        float s = v.x * v.x + v.y * v.y + v.z * v.z + v.w * v.w;
        float sp = (threadIdx.x < KSCR / 4) ? s : 0.f;   // first 32 floats = float4 0..7

        __shared__ float red[8];
        float st = s;
        #pragma unroll
        for (int o = 16; o > 0; o >>= 1) st += __shfl_xor_sync(0xffffffffu, st, o);
        #pragma unroll
        for (int o = 16; o > 0; o >>= 1) sp += __shfl_xor_sync(0xffffffffu, sp, o);
        if ((threadIdx.x & 31) == 0) red[threadIdx.x >> 5] = st;
        __syncthreads();
        if (threadIdx.x == 0) {
            float t = 0.f;
            #pragma unroll
            for (int w = 0; w < 8; w++) t += red[w];
            g_sq[row] = t;
            g_p[row] = sp;   // warp 0 lane 0 holds partial sum over dims [0,32)
        }
    } else {
        // Bucketing block: warp w compacts rows with lab==w, in row order
        // (deterministic: ballot + prefix-popc).
        int w = threadIdx.x >> 5;
        int lane = threadIdx.x & 31;
        unsigned lt = (1u << lane) - 1u;
        int cnt = 0;
        for (int base = 0; base < BDIM; base += 32) {
            int l = lab[base + lane];
            unsigned m = __ballot_sync(0xffffffffu, l == w);
            if (l == w) g_idx[w][cnt + __popc(m & lt)] = base + lane;
            cnt += __popc(m);
        }
        if (lane == 0) g_cnt[w] = cnt;
    }
}

// ---------------------------------------------------------------------------
// Kernel 2: diagonal contribution. dist(i,i) in the reference is
// sqrt(2*(sq_i - dot_ii)) where dot_ii comes from cublas SGEMM: a SINGLE
// accumulator, strictly sequential FMA over k in natural order. The fmaf
// chain is serially dependent, so the compiler cannot reassociate it.
// This path produces essentially the ENTIRE loss value.
// ---------------------------------------------------------------------------
__global__ void __launch_bounds__(32) diag_kernel(const float* __restrict__ f,
                                                  const int* __restrict__ lab) {
    int row = blockIdx.x * 32 + threadIdx.x;
    const float4* fr = (const float4*)(f + (size_t)row * DDIM);
    float acc = 0.f;
    for (int k = 0; k < DDIM / 4; k++) {
        float4 v = fr[k];
        acc = fmaf(v.x, v.x, acc);
        acc = fmaf(v.y, v.y, acc);
        acc = fmaf(v.z, v.z, acc);
        acc = fmaf(v.w, v.w, acc);
    }
    float r = 2.0f * (g_sq[row] - acc);       // residual d2 on the diagonal
    float dist = (r > 0.f) ? sqrtf(r) : 0.f;  // matches where(d2>0, sqrt, 0)
    float val = 1.0f - dist;                  // MARGIN - dist
    if (val > 0.f) atomicAdd(&g_domsum[lab[row]], val);
}

// ---------------------------------------------------------------------------
// Exact fallback for screened-in pairs: reference-order (cublas-like)
// sequential dot, then the reference hinge. Expected calls: ~100 total.
// ---------------------------------------------------------------------------
__device__ float pair_val_exact(const float* __restrict__ f, int i, int j) {
    const float4* a = (const float4*)(f + (size_t)i * DDIM);
    const float4* b = (const float4*)(f + (size_t)j * DDIM);
    float acc = 0.f;
    for (int k = 0; k < DDIM / 4; k++) {
        float4 va = a[k], vb = b[k];
        acc = fmaf(va.x, vb.x, acc);
        acc = fmaf(va.y, vb.y, acc);
        acc = fmaf(va.z, vb.z, acc);
        acc = fmaf(va.w, vb.w, acc);
    }
    float d2 = g_sq[i] + g_sq[j] - 2.0f * acc;
    float dist = (d2 > 0.f) ? sqrtf(d2) : 0.f;
    return 1.0f - dist;
}

// ---------------------------------------------------------------------------
// Kernel 3: within-domain K=32 screening + fused finalize.
// grid = (MAXTRI, NDOM). Block (t, dom) handles tri-tile t of domain dom's
// bucketed rows (64x64 tile); tiles past the domain's size exit early but
// still arrive at the completion counter. partial_d2 >= SCREEN_THRESH
// provably zeroes the hinge; rare survivors get the exact recheck.
// The last block to arrive computes the final scalar and RESETS the
// accumulators so the next graph replay starts from a clean state.
// ---------------------------------------------------------------------------
__global__ void __launch_bounds__(256) screen_finalize_kernel(const float* __restrict__ f,
                                                              float* __restrict__ out) {
    __shared__ float As[TILE][KSCR + 1];
    __shared__ float Bs[TILE][KSCR + 1];
    __shared__ float pA[TILE], pB[TILE];
    __shared__ int   iA[TILE], iB[TILE];

    int dom = blockIdx.y;
    int n = g_cnt[dom];
    int nt = (n + TILE - 1) / TILE;

    // tri id -> (ti, tj), ti >= tj
    int t = blockIdx.x;
    int ti = (int)((sqrtf(8.0f * (float)t + 1.0f) - 1.0f) * 0.5f);
    while ((ti + 1) * (ti + 2) / 2 <= t) ++ti;
    while (ti * (ti + 1) / 2 > t) --ti;
    int tj = t - ti * (ti + 1) / 2;

    bool active = (ti < nt);   // block-uniform
    if (active) {
        // Load tiles: 256 threads, thread -> (row lr, two float4s q and q+4).
        int lr = threadIdx.x >> 2;
        int q0 = threadIdx.x & 3;
        int ra = ti * TILE + lr;
        int rb = tj * TILE + lr;
        int rowA = (ra < n) ? g_idx[dom][ra] : g_idx[dom][0];
        int rowB = (rb < n) ? g_idx[dom][rb] : g_idx[dom][0];
        if (q0 == 0) {
            pA[lr] = (ra < n) ? g_p[rowA] : 1e30f;   // pad rows can never survive
            pB[lr] = (rb < n) ? g_p[rowB] : 1e30f;
            iA[lr] = rowA;
            iB[lr] = rowB;
        }
        const float4* fa = (const float4*)(f + (size_t)rowA * DDIM);
        const float4* fb = (const float4*)(f + (size_t)rowB * DDIM);
        #pragma unroll
        for (int qq = 0; qq < 2; qq++) {
            int q = q0 + 4 * qq;
            float4 va = fa[q];
            float4 vb = fb[q];
            int c = q * 4;
            As[lr][c + 0] = va.x; As[lr][c + 1] = va.y;
            As[lr][c + 2] = va.z; As[lr][c + 3] = va.w;
            Bs[lr][c + 0] = vb.x; Bs[lr][c + 1] = vb.y;
            Bs[lr][c + 2] = vb.z; Bs[lr][c + 3] = vb.w;
        }
        __syncthreads();

        int tx = threadIdx.x & 15;
        int ty = threadIdx.x >> 4;

        float c[4][4];
        #pragma unroll
        for (int qa = 0; qa < 4; qa++)
            #pragma unroll
            for (int qb = 0; qb < 4; qb++) c[qa][qb] = 0.f;

        #pragma unroll
        for (int kk = 0; kk < KSCR; kk++) {
            float a[4], b[4];
            #pragma unroll
            for (int q = 0; q < 4; q++) a[q] = As[ty + 16 * q][kk];
            #pragma unroll
            for (int q = 0; q < 4; q++) b[q] = Bs[tx + 16 * q][kk];
            #pragma unroll
            for (int qa = 0; qa < 4; qa++)
                #pragma unroll
                for (int qb = 0; qb < 4; qb++)
                    c[qa][qb] += a[qa] * b[qb];
        }

        // Epilogue: lower-bound test; rare survivors -> exact recheck.
        #pragma unroll
        for (int qa = 0; qa < 4; qa++) {
            int r = ty + 16 * qa;
            float pi = pA[r];
            #pragma unroll
            for (int qb = 0; qb < 4; qb++) {
                int cc = tx + 16 * qb;
                if (ti == tj && cc >= r) continue;   // strict lower triangle
                float d2p = pi + pB[cc] - 2.0f * c[qa][qb];
                if (d2p < SCREEN_THRESH) {
                    float val = pair_val_exact(f, iA[r], iB[cc]);
                    if (val > 0.f) atomicAdd(&g_domsum[dom], 2.0f * val);
                }
            }
        }
    }

    // Fused finalize: every block (active or not) arrives; last one reduces.
    __syncthreads();
    if (threadIdx.x == 0) {
        __threadfence();
        unsigned int ticket = atomicAdd(&g_arrive, 1u);
        if (ticket == (unsigned int)(gridDim.x * gridDim.y) - 1u) {
            volatile float* ds = g_domsum;
            float acc = 0.f, cnt = 0.f;
            #pragma unroll
            for (int d = 0; d < NDOM; d++) {
                int nd = g_cnt[d];
                if (nd > 1) {
                    acc += ds[d] / (float)(nd * nd);
                    cnt += 1.f;
                }
            }
            *out = (cnt > 0.f) ? (acc / cnt) : 0.f;
            // Reset state for the next graph replay.
            #pragma unroll
            for (int d = 0; d < NDOM; d++) atomicExch(&g_domsum[d], 0.f);
            __threadfence();
            atomicExch(&g_arrive, 0u);
        }
    }
}

extern "C" void kernel_launch(void* const* d_in, const int* in_sizes, int n_in,
                              void* d_out, int out_size) {
    const float* f   = (const float*)d_in[0];
    const int*   lab = (const int*)d_in[1];
    (void)in_sizes; (void)n_in; (void)out_size;

    sqnorm_bucket_kernel<<<BDIM + 1, 256>>>(f, lab);
    diag_kernel<<<BDIM / 32, 32>>>(f, lab);
    dim3 grid(MAXTRI, NDOM);
    screen_finalize_kernel<<<grid, 256>>>(f, (float*)d_out);
}

// round 9
// speedup vs baseline: 19.7314x; 1.1312x over previous
#include <cuda_runtime.h>
#include <math.h>

#define BDIM 4096
#define DDIM 1024
#define NDOM 8
#define KSCR 32                 // screening dims (rigorous lower bound on d^2)
#define TILE 64
#define MAXNT 16                // supports bucket sizes up to 1024 (mean 512, sd 21)
#define MAXTRI (MAXNT * (MAXNT + 1) / 2)   // 136 tri-tiles per domain
#define SCREEN_THRESH 4.0f      // partial-d2 over 32 dims: mean 64, sigma 16 -> z=-3.75

// Scratch (no allocations allowed). Zero at module load; the screen kernel's
// finalizer resets g_domsum/g_arrive after every run so graph replays are clean.
__device__ float g_sq[BDIM];          // full squared norms (warp tree reduce)
__device__ float g_p[BDIM];           // partial squared norms over first KSCR dims
__device__ int   g_idx[NDOM][BDIM];   // per-domain compacted row indices
__device__ int   g_cnt[NDOM];         // per-domain counts
__device__ float g_domsum[NDOM];      // per-domain hinge sums
__device__ unsigned int g_arrive;     // completion counter for fused finalize

// ---------------------------------------------------------------------------
// Kernel 1 (fused): blocks 0..511: warp-per-row. Each warp
//   (a) loads its row with 8 float4s per lane (coalesced, MLP=8), staging
//       the row into shared memory,
//   (b) warp-reduces the full squared norm (tree; mimics XLA reduce's small
//       error) and the partial norm over the first KSCR dims,
//   (c) lane 0 replays the reference diagonal: dot_ii as a SINGLE-accumulator
//       strictly sequential fmaf chain over k=0..1023 in natural order
//       (cublas SGEMM accumulation structure; serially dependent, so the
//       compiler cannot reassociate), then dist=sqrt(2*(sq-dot)) and the
//       hinge. This path produces essentially the ENTIRE loss value.
// Block 512: deterministic warp-ballot bucketing of rows by domain.
// ---------------------------------------------------------------------------
__global__ void __launch_bounds__(256) fused_front_kernel(const float* __restrict__ f,
                                                          const int* __restrict__ lab) {
    if (blockIdx.x == BDIM / 8) {
        // Bucketing block: warp w compacts rows with lab==w, in row order.
        int w = threadIdx.x >> 5;
        int lane = threadIdx.x & 31;
        unsigned lt = (1u << lane) - 1u;
        int cnt = 0;
        for (int base = 0; base < BDIM; base += 32) {
            int l = lab[base + lane];
            unsigned m = __ballot_sync(0xffffffffu, l == w);
            if (l == w) g_idx[w][cnt + __popc(m & lt)] = base + lane;
            cnt += __popc(m);
        }
        if (lane == 0) g_cnt[w] = cnt;
        return;
    }

    __shared__ float4 buf[8][DDIM / 4];   // 8 warps x 4KB row stage = 32KB
    int w = threadIdx.x >> 5;
    int lane = threadIdx.x & 31;
    int row = blockIdx.x * 8 + w;
    const float4* fr = (const float4*)(f + (size_t)row * DDIM);

    float s = 0.f, sp = 0.f;
    #pragma unroll
    for (int q = 0; q < 8; q++) {
        float4 v = fr[lane + 32 * q];
        buf[w][lane + 32 * q] = v;
        float t = v.x * v.x + v.y * v.y + v.z * v.z + v.w * v.w;
        s += t;
        if (q == 0 && lane < KSCR / 4) sp += t;   // float4 idx 0..7 = dims [0,32)
    }
    #pragma unroll
    for (int o = 16; o > 0; o >>= 1) {
        s  += __shfl_xor_sync(0xffffffffu, s,  o);
        sp += __shfl_xor_sync(0xffffffffu, sp, o);
    }
    __syncwarp();   // buf[w] writes by all lanes visible to lane 0

    if (lane == 0) {
        g_sq[row] = s;
        g_p[row]  = sp;
        // Reference-order sequential diagonal dot (single accumulator).
        float acc = 0.f;
        const float4* b = buf[w];
        #pragma unroll 8
        for (int k = 0; k < DDIM / 4; k++) {
            float4 v = b[k];
            acc = fmaf(v.x, v.x, acc);
            acc = fmaf(v.y, v.y, acc);
            acc = fmaf(v.z, v.z, acc);
            acc = fmaf(v.w, v.w, acc);
        }
        float r = 2.0f * (s - acc);               // diagonal d2 residual
        float dist = (r > 0.f) ? sqrtf(r) : 0.f;  // where(d2>0, sqrt, 0)
        float val = 1.0f - dist;                  // MARGIN - dist
        if (val > 0.f) atomicAdd(&g_domsum[lab[row]], val);
    }
}

// ---------------------------------------------------------------------------
// Exact fallback for screened-in pairs: reference-order (cublas-like)
// sequential dot, then the reference hinge. Expected calls: ~100 total.
// ---------------------------------------------------------------------------
__device__ float pair_val_exact(const float* __restrict__ f, int i, int j) {
    const float4* a = (const float4*)(f + (size_t)i * DDIM);
    const float4* b = (const float4*)(f + (size_t)j * DDIM);
    float acc = 0.f;
    for (int k = 0; k < DDIM / 4; k++) {
        float4 va = a[k], vb = b[k];
        acc = fmaf(va.x, vb.x, acc);
        acc = fmaf(va.y, vb.y, acc);
        acc = fmaf(va.z, vb.z, acc);
        acc = fmaf(va.w, vb.w, acc);
    }
    float d2 = g_sq[i] + g_sq[j] - 2.0f * acc;
    float dist = (d2 > 0.f) ? sqrtf(d2) : 0.f;
    return 1.0f - dist;
}

// ---------------------------------------------------------------------------
// Kernel 2: within-domain K=32 screening + fused finalize.
// grid = (MAXTRI, NDOM). Block (t, dom) handles tri-tile t of domain dom's
// bucketed rows; tiles past the domain's size exit early but still arrive.
// partial_d2 >= SCREEN_THRESH provably zeroes the hinge (sum of squares over
// the remaining 992 dims is >= 0); rare survivors get the exact recheck.
// Last block reduces and RESETS accumulators for the next graph replay.
// ---------------------------------------------------------------------------
__global__ void __launch_bounds__(256) screen_finalize_kernel(const float* __restrict__ f,
                                                              float* __restrict__ out) {
    __shared__ float As[TILE][KSCR + 1];
    __shared__ float Bs[TILE][KSCR + 1];
    __shared__ float pA[TILE], pB[TILE];
    __shared__ int   iA[TILE], iB[TILE];

    int dom = blockIdx.y;
    int n = g_cnt[dom];
    int nt = (n + TILE - 1) / TILE;

    // tri id -> (ti, tj), ti >= tj
    int t = blockIdx.x;
    int ti = (int)((sqrtf(8.0f * (float)t + 1.0f) - 1.0f) * 0.5f);
    while ((ti + 1) * (ti + 2) / 2 <= t) ++ti;
    while (ti * (ti + 1) / 2 > t) --ti;
    int tj = t - ti * (ti + 1) / 2;

    bool active = (ti < nt);   // block-uniform
    if (active) {
        int lr = threadIdx.x >> 2;
        int q0 = threadIdx.x & 3;
        int ra = ti * TILE + lr;
        int rb = tj * TILE + lr;
        int rowA = (ra < n) ? g_idx[dom][ra] : g_idx[dom][0];
        int rowB = (rb < n) ? g_idx[dom][rb] : g_idx[dom][0];
        if (q0 == 0) {
            pA[lr] = (ra < n) ? g_p[rowA] : 1e30f;   // pad rows can never survive
            pB[lr] = (rb < n) ? g_p[rowB] : 1e30f;
            iA[lr] = rowA;
            iB[lr] = rowB;
        }
        const float4* fa = (const float4*)(f + (size_t)rowA * DDIM);
        const float4* fb = (const float4*)(f + (size_t)rowB * DDIM);
        #pragma unroll
        for (int qq = 0; qq < 2; qq++) {
            int q = q0 + 4 * qq;
            float4 va = fa[q];
            float4 vb = fb[q];
            int c = q * 4;
            As[lr][c + 0] = va.x; As[lr][c + 1] = va.y;
            As[lr][c + 2] = va.z; As[lr][c + 3] = va.w;
            Bs[lr][c + 0] = vb.x; Bs[lr][c + 1] = vb.y;
            Bs[lr][c + 2] = vb.z; Bs[lr][c + 3] = vb.w;
        }
        __syncthreads();

        int tx = threadIdx.x & 15;
        int ty = threadIdx.x >> 4;

        float c[4][4];
        #pragma unroll
        for (int qa = 0; qa < 4; qa++)
            #pragma unroll
            for (int qb = 0; qb < 4; qb++) c[qa][qb] = 0.f;

        #pragma unroll
        for (int kk = 0; kk < KSCR; kk++) {
            float a[4], b[4];
            #pragma unroll
            for (int q = 0; q < 4; q++) a[q] = As[ty + 16 * q][kk];
            #pragma unroll
            for (int q = 0; q < 4; q++) b[q] = Bs[tx + 16 * q][kk];
            #pragma unroll
            for (int qa = 0; qa < 4; qa++)
                #pragma unroll
                for (int qb = 0; qb < 4; qb++)
                    c[qa][qb] += a[qa] * b[qb];
        }

        // Epilogue: lower-bound test; rare survivors -> exact recheck.
        #pragma unroll
        for (int qa = 0; qa < 4; qa++) {
            int r = ty + 16 * qa;
            float pi = pA[r];
            #pragma unroll
            for (int qb = 0; qb < 4; qb++) {
                int cc = tx + 16 * qb;
                if (ti == tj && cc >= r) continue;   // strict lower triangle
                float d2p = pi + pB[cc] - 2.0f * c[qa][qb];
                if (d2p < SCREEN_THRESH) {
                    float val = pair_val_exact(f, iA[r], iB[cc]);
                    if (val > 0.f) atomicAdd(&g_domsum[dom], 2.0f * val);
                }
            }
        }
    }

    // Fused finalize: every block (active or not) arrives; last one reduces.
    __syncthreads();
    if (threadIdx.x == 0) {
        __threadfence();
        unsigned int ticket = atomicAdd(&g_arrive, 1u);
        if (ticket == (unsigned int)(gridDim.x * gridDim.y) - 1u) {
            volatile float* ds = g_domsum;
            float acc = 0.f, cnt = 0.f;
            #pragma unroll
            for (int d = 0; d < NDOM; d++) {
                int nd = g_cnt[d];
                if (nd > 1) {
                    acc += ds[d] / (float)(nd * nd);
                    cnt += 1.f;
                }
            }
            *out = (cnt > 0.f) ? (acc / cnt) : 0.f;
            // Reset state for the next graph replay.
            #pragma unroll
            for (int d = 0; d < NDOM; d++) atomicExch(&g_domsum[d], 0.f);
            __threadfence();
            atomicExch(&g_arrive, 0u);
        }
    }
}

extern "C" void kernel_launch(void* const* d_in, const int* in_sizes, int n_in,
                              void* d_out, int out_size) {
    const float* f   = (const float*)d_in[0];
    const int*   lab = (const int*)d_in[1];
    (void)in_sizes; (void)n_in; (void)out_size;

    fused_front_kernel<<<BDIM / 8 + 1, 256>>>(f, lab);   // 512 row-blocks + 1 bucket block
    dim3 grid(MAXTRI, NDOM);
    screen_finalize_kernel<<<grid, 256>>>(f, (float*)d_out);
}

// round 12
// speedup vs baseline: 26.9389x; 1.3653x over previous
#include <cuda_runtime.h>
#include <math.h>

#define BDIM 4096
#define DDIM 1024
#define NDOM 8
#define KSCR 32                 // screening dims (rigorous lower bound on d^2)
#define TILE 64
#define MAXNT 10                // buckets up to 640 rows = mean 512 + 6 sigma
#define MAXTRI (MAXNT * (MAXNT + 1) / 2)   // 55 tri-tiles per domain
#define SCREEN_THRESH 4.0f      // partial-d2 over 32 dims: mean 64, sigma 16
#define RSTRIDE 1028            // smem row stride (floats): 16B-aligned, conflict-free

// Scratch (no allocations allowed). Zero at module load; the screen kernel's
// finalizer resets g_domsum/g_arrive after every run so graph replays are clean.
__device__ float g_sq[BDIM];          // full squared norms (warp tree reduce)
__device__ float g_p[BDIM];           // partial squared norms over first KSCR dims
__device__ int   g_idx[NDOM][BDIM];   // per-domain compacted row indices
__device__ int   g_cnt[NDOM];         // per-domain counts
__device__ float g_domsum[NDOM];      // per-domain hinge sums
__device__ unsigned int g_arrive;     // completion counter for fused finalize

// ---------------------------------------------------------------------------
// Kernel 1 (fused front): blocks 0..511 each own 8 rows (warp w -> row 8b+w).
//   (a) warp w loads its row coalesced (8 float4/lane, MLP=8), stages it into
//       smem at stride RSTRIDE, and tree-reduces g_sq / g_p (same shapes as
//       the previous passing kernel -> identical values).
//   (b) after __syncthreads, warp 0 lanes 0..7 run the 8 diagonal chains
//       SIMULTANEOUSLY: lane l replays the reference dot_ii for row l as a
//       SINGLE-accumulator strictly sequential fmaf chain over k=0..1023 in
//       natural order (cublas SGEMM accumulation structure; serially
//       dependent, unreorderable). Packing 8 chains per warp instruction cuts
//       FMA-slot pressure 8x vs one chain per warp; per-chain math is
//       bit-identical. This path produces essentially the ENTIRE loss value.
// Block 512: deterministic warp-ballot bucketing of rows by domain.
// ---------------------------------------------------------------------------
__global__ void __launch_bounds__(256) fused_front_kernel(const float* __restrict__ f,
                                                          const int* __restrict__ lab) {
    if (blockIdx.x == BDIM / 8) {
        // Bucketing block: warp w compacts rows with lab==w, in row order.
        int w = threadIdx.x >> 5;
        int lane = threadIdx.x & 31;
        unsigned lt = (1u << lane) - 1u;
        int cnt = 0;
        for (int base = 0; base < BDIM; base += 32) {
            int l = lab[base + lane];
            unsigned m = __ballot_sync(0xffffffffu, l == w);
            if (l == w) g_idx[w][cnt + __popc(m & lt)] = base + lane;
            cnt += __popc(m);
        }
        if (lane == 0) g_cnt[w] = cnt;
        return;
    }

    __shared__ __align__(16) float buf[8][RSTRIDE];   // 8 rows staged, ~32.9 KB
    __shared__ float sqs[8];                          // per-row full sq norms
    int w = threadIdx.x >> 5;
    int lane = threadIdx.x & 31;
    int row = blockIdx.x * 8 + w;
    const float4* fr = (const float4*)(f + (size_t)row * DDIM);

    float s = 0.f, sp = 0.f;
    #pragma unroll
    for (int q = 0; q < 8; q++) {
        float4 v = fr[lane + 32 * q];
        *(float4*)&buf[w][4 * (lane + 32 * q)] = v;
        float t = v.x * v.x + v.y * v.y + v.z * v.z + v.w * v.w;
        s += t;
        if (q == 0 && lane < KSCR / 4) sp += t;   // float4 idx 0..7 = dims [0,32)
    }
    #pragma unroll
    for (int o = 16; o > 0; o >>= 1) {
        s  += __shfl_xor_sync(0xffffffffu, s,  o);
        sp += __shfl_xor_sync(0xffffffffu, sp, o);
    }
    if (lane == 0) {
        g_sq[row] = s;
        g_p[row]  = sp;
        sqs[w]    = s;
    }
    __syncthreads();   // all warps participate; staging + sqs visible below

    if (w == 0 && lane < 8) {
        // 8 packed chains: lane l owns row blockIdx.x*8 + l.
        int crow = blockIdx.x * 8 + lane;
        const float* bp = buf[lane];
        float acc = 0.f;
        #pragma unroll 8
        for (int k = 0; k < DDIM; k += 4) {
            float4 v = *(const float4*)(bp + k);   // conflict-free LDS.128
            acc = fmaf(v.x, v.x, acc);
            acc = fmaf(v.y, v.y, acc);
            acc = fmaf(v.z, v.z, acc);
            acc = fmaf(v.w, v.w, acc);
        }
        float r = 2.0f * (sqs[lane] - acc);       // diagonal d2 residual
        float dist = (r > 0.f) ? sqrtf(r) : 0.f;  // where(d2>0, sqrt, 0)
        float val = 1.0f - dist;                  // MARGIN - dist
        if (val > 0.f) atomicAdd(&g_domsum[lab[crow]], val);
    }
}

// ---------------------------------------------------------------------------
// Exact fallback for screened-in pairs: reference-order (cublas-like)
// sequential dot, then the reference hinge. Expected calls: ~100 total.
// ---------------------------------------------------------------------------
__device__ float pair_val_exact(const float* __restrict__ f, int i, int j) {
    const float4* a = (const float4*)(f + (size_t)i * DDIM);
    const float4* b = (const float4*)(f + (size_t)j * DDIM);
    float acc = 0.f;
    for (int k = 0; k < DDIM / 4; k++) {
        float4 va = a[k], vb = b[k];
        acc = fmaf(va.x, vb.x, acc);
        acc = fmaf(va.y, vb.y, acc);
        acc = fmaf(va.z, vb.z, acc);
        acc = fmaf(va.w, vb.w, acc);
    }
    float d2 = g_sq[i] + g_sq[j] - 2.0f * acc;
    float dist = (d2 > 0.f) ? sqrtf(d2) : 0.f;
    return 1.0f - dist;
}

// ---------------------------------------------------------------------------
// Kernel 2: within-domain K=32 screening + fused finalize.
// grid = (MAXTRI, NDOM), now sized for buckets <= 640 (mean+6sigma) so the
// dead second wave of inactive blocks is gone. partial_d2 >= SCREEN_THRESH
// provably zeroes the hinge; rare survivors get the exact recheck.
// Completion uses a RELEASE atomic ticket (no per-block L1-flushing
// __threadfence); the single winner issues one acq_rel fence, reduces, and
// RESETS accumulators for the next graph replay.
// ---------------------------------------------------------------------------
__global__ void __launch_bounds__(256) screen_finalize_kernel(const float* __restrict__ f,
                                                              float* __restrict__ out) {
    __shared__ float As[TILE][KSCR + 1];
    __shared__ float Bs[TILE][KSCR + 1];
    __shared__ float pA[TILE], pB[TILE];
    __shared__ int   iA[TILE], iB[TILE];

    int dom = blockIdx.y;
    int n = g_cnt[dom];
    int nt = (n + TILE - 1) / TILE;

    // tri id -> (ti, tj), ti >= tj
    int t = blockIdx.x;
    int ti = (int)((sqrtf(8.0f * (float)t + 1.0f) - 1.0f) * 0.5f);
    while ((ti + 1) * (ti + 2) / 2 <= t) ++ti;
    while (ti * (ti + 1) / 2 > t) --ti;
    int tj = t - ti * (ti + 1) / 2;

    bool active = (ti < nt);   // block-uniform
    if (active) {
        int lr = threadIdx.x >> 2;
        int q0 = threadIdx.x & 3;
        int ra = ti * TILE + lr;
        int rb = tj * TILE + lr;
        int rowA = (ra < n) ? g_idx[dom][ra] : g_idx[dom][0];
        int rowB = (rb < n) ? g_idx[dom][rb] : g_idx[dom][0];
        if (q0 == 0) {
            pA[lr] = (ra < n) ? g_p[rowA] : 1e30f;   // pad rows can never survive
            pB[lr] = (rb < n) ? g_p[rowB] : 1e30f;
            iA[lr] = rowA;
            iB[lr] = rowB;
        }
        const float4* fa = (const float4*)(f + (size_t)rowA * DDIM);
        const float4* fb = (const float4*)(f + (size_t)rowB * DDIM);
        #pragma unroll
        for (int qq = 0; qq < 2; qq++) {
            int q = q0 + 4 * qq;
            float4 va = fa[q];
            float4 vb = fb[q];
            int c = q * 4;
            As[lr][c + 0] = va.x; As[lr][c + 1] = va.y;
            As[lr][c + 2] = va.z; As[lr][c + 3] = va.w;
            Bs[lr][c + 0] = vb.x; Bs[lr][c + 1] = vb.y;
            Bs[lr][c + 2] = vb.z; Bs[lr][c + 3] = vb.w;
        }
        __syncthreads();

        int tx = threadIdx.x & 15;
        int ty = threadIdx.x >> 4;

        float c[4][4];
        #pragma unroll
        for (int qa = 0; qa < 4; qa++)
            #pragma unroll
            for (int qb = 0; qb < 4; qb++) c[qa][qb] = 0.f;

        #pragma unroll
        for (int kk = 0; kk < KSCR; kk++) {
            float a[4], b[4];
            #pragma unroll
            for (int q = 0; q < 4; q++) a[q] = As[ty + 16 * q][kk];
            #pragma unroll
            for (int q = 0; q < 4; q++) b[q] = Bs[tx + 16 * q][kk];
            #pragma unroll
            for (int qa = 0; qa < 4; qa++)
                #pragma unroll
                for (int qb = 0; qb < 4; qb++)
                    c[qa][qb] += a[qa] * b[qb];
        }

        // Epilogue: lower-bound test; rare survivors -> exact recheck.
        #pragma unroll
        for (int qa = 0; qa < 4; qa++) {
            int r = ty + 16 * qa;
            float pi = pA[r];
            #pragma unroll
            for (int qb = 0; qb < 4; qb++) {
                int cc = tx + 16 * qb;
                if (ti == tj && cc >= r) continue;   // strict lower triangle
                float d2p = pi + pB[cc] - 2.0f * c[qa][qb];
                if (d2p < SCREEN_THRESH) {
                    float val = pair_val_exact(f, iA[r], iB[cc]);
                    if (val > 0.f) atomicAdd(&g_domsum[dom], 2.0f * val);
                }
            }
        }
    }

    // Fused finalize: release-ticket arrival; last block reduces + resets.
    __syncthreads();
    if (threadIdx.x == 0) {
        unsigned int ticket;
        asm volatile("atom.release.gpu.global.add.u32 %0, [%1], %2;"
                     : "=r"(ticket) : "l"(&g_arrive), "r"(1u) : "memory");
        if (ticket == (unsigned int)(gridDim.x * gridDim.y) - 1u) {
            asm volatile("fence.acq_rel.gpu;" ::: "memory");
            volatile float* ds = g_domsum;
            float acc = 0.f, cnt = 0.f;
            #pragma unroll
            for (int d = 0; d < NDOM; d++) {
                int nd = g_cnt[d];
                if (nd > 1) {
                    acc += ds[d] / (float)(nd * nd);
                    cnt += 1.f;
                }
            }
            *out = (cnt > 0.f) ? (acc / cnt) : 0.f;
            // Reset state for the next graph replay (kernel boundary orders
            // these before the next launch's reads).
            #pragma unroll
            for (int d = 0; d < NDOM; d++) atomicExch(&g_domsum[d], 0.f);
            atomicExch(&g_arrive, 0u);
        }
    }
}

extern "C" void kernel_launch(void* const* d_in, const int* in_sizes, int n_in,
                              void* d_out, int out_size) {
    const float* f   = (const float*)d_in[0];
    const int*   lab = (const int*)d_in[1];
    (void)in_sizes; (void)n_in; (void)out_size;

    fused_front_kernel<<<BDIM / 8 + 1, 256>>>(f, lab);   // 512 row-blocks + 1 bucket block
    dim3 grid(MAXTRI, NDOM);
    screen_finalize_kernel<<<grid, 256>>>(f, (float*)d_out);
}

// round 13
// speedup vs baseline: 29.5671x; 1.0976x over previous
#include <cuda_runtime.h>
#include <math.h>

#define BDIM 4096
#define DDIM 1024
#define NDOM 8
#define KSCR 32                 // screening dims (rigorous lower bound on d^2)
#define TILE 64
#define MAXNT 10                // buckets up to 640 rows = mean 512 + 6 sigma
#define MAXTRI (MAXNT * (MAXNT + 1) / 2)   // 55 tri-tiles per domain
#define NSCREEN (NDOM * MAXTRI)            // 440 screen blocks
#define NFRONT (BDIM / 8)                  // 512 front blocks
#define NBLK (NFRONT + 1)                  // +1 bucketing block = 513
#define SCREEN_THRESH 4.0f      // partial-d2 over 32 dims: mean 64, sigma 16
#define RSTRIDE 1028            // front smem row stride (floats), conflict-free
#define KPAD 36                 // screen smem k-stride: 16B-aligned float4 loads

// Scratch (no allocations allowed). Zero at module load; the finalizer resets
// all counters/accumulators after every run so graph replays are clean.
__device__ float g_sq[BDIM];          // full squared norms (warp-tree shape)
__device__ float g_p[BDIM];           // partial squared norms over first KSCR dims
__device__ int   g_idx[NDOM][BDIM];   // per-domain compacted row indices
__device__ int   g_cnt[NDOM];         // per-domain counts
__device__ float g_domsum[NDOM];      // per-domain hinge sums
__device__ unsigned int g_arrive1;    // phase-A completion counter
__device__ unsigned int g_arrive2;    // whole-grid completion counter

struct SmemFront {
    float buf[8][RSTRIDE];   // 8 staged rows (~32.9 KB)
    float sqs[8];
};
struct SmemScreen {
    float As[TILE][KPAD];
    float Bs[TILE][KPAD];
    float pA[TILE], pB[TILE];
    int   iA[TILE], iB[TILE];
};
union SmemU { SmemFront fr; SmemScreen sc; };

__device__ __forceinline__ unsigned int atom_add_release(unsigned int* p, unsigned int v) {
    unsigned int old;
    asm volatile("atom.release.gpu.global.add.u32 %0, [%1], %2;"
                 : "=r"(old) : "l"(p), "r"(v) : "memory");
    return old;
}
__device__ __forceinline__ unsigned int ld_acquire(unsigned int* p) {
    unsigned int v;
    asm volatile("ld.acquire.gpu.global.u32 %0, [%1];" : "=r"(v) : "l"(p) : "memory");
    return v;
}

// ---------------------------------------------------------------------------
// Exact fallback for screened-in pairs: reference-order (cublas-like)
// sequential dot, then the reference hinge. Expected calls: ~100 total.
// ---------------------------------------------------------------------------
__device__ float pair_val_exact(const float* __restrict__ f, int i, int j) {
    const float4* a = (const float4*)(f + (size_t)i * DDIM);
    const float4* b = (const float4*)(f + (size_t)j * DDIM);
    float acc = 0.f;
    for (int k = 0; k < DDIM / 4; k++) {
        float4 va = a[k], vb = b[k];
        acc = fmaf(va.x, vb.x, acc);
        acc = fmaf(va.y, vb.y, acc);
        acc = fmaf(va.z, vb.z, acc);
        acc = fmaf(va.w, vb.w, acc);
    }
    float d2 = g_sq[i] + g_sq[j] - 2.0f * acc;
    float dist = (d2 > 0.f) ? sqrtf(d2) : 0.f;
    return 1.0f - dist;
}

// ---------------------------------------------------------------------------
// Single fused kernel. Phases (per block):
//   A) bid<512: warp w loads row 8*bid+w coalesced, stages in smem, tree-
//      reduces g_sq/g_p (shapes identical to prior passing kernel); post
//      arrive1 (release); warp-0 lanes 0..7 run the 8 packed diagonal chains
//      (reference cublas accumulation: single-accumulator sequential fmaf,
//      k ascending -> serially dependent, unreorderable). bid==512: ballot
//      bucketing of rows by domain; post arrive1.
//   B) bid<440: spin-acquire arrive1==513, then within-domain K=32 screen
//      (rigorous lower bound; survivors -> exact recheck). Non-screen blocks
//      skip the spin and exit via arrive2 (guarantees forward progress even
//      at 3 blocks/SM co-residency).
//   C) release ticket arrive2; last block fences, reduces, writes the scalar,
//      and resets all device state for the next graph replay.
// ---------------------------------------------------------------------------
__global__ void __launch_bounds__(256, 4) fused_all_kernel(const float* __restrict__ f,
                                                           const int* __restrict__ lab,
                                                           float* __restrict__ out) {
    __shared__ SmemU sm;
    int bid  = blockIdx.x;
    int w    = threadIdx.x >> 5;
    int lane = threadIdx.x & 31;

    // ---------------- Phase A ----------------
    if (bid < NFRONT) {
        int row = bid * 8 + w;
        const float4* fr = (const float4*)(f + (size_t)row * DDIM);
        float s = 0.f, sp = 0.f;
        #pragma unroll
        for (int q = 0; q < 8; q++) {
            float4 v = fr[lane + 32 * q];
            *(float4*)&sm.fr.buf[w][4 * (lane + 32 * q)] = v;
            float t = v.x * v.x + v.y * v.y + v.z * v.z + v.w * v.w;
            s += t;
            if (q == 0 && lane < KSCR / 4) sp += t;   // dims [0,32)
        }
        #pragma unroll
        for (int o = 16; o > 0; o >>= 1) {
            s  += __shfl_xor_sync(0xffffffffu, s,  o);
            sp += __shfl_xor_sync(0xffffffffu, sp, o);
        }
        if (lane == 0) {
            g_sq[row] = s;
            g_p[row]  = sp;
            sm.fr.sqs[w] = s;
        }
        __syncthreads();   // staging + sqs + all warps' g_sq/g_p stores done
        if (threadIdx.x == 0) atom_add_release(&g_arrive1, 1u);  // cumulative release

        if (w == 0 && lane < 8) {
            // 8 packed reference chains: lane l owns row bid*8 + l.
            int crow = bid * 8 + lane;
            const float* bp = sm.fr.buf[lane];
            float acc = 0.f;
            #pragma unroll 8
            for (int k = 0; k < DDIM; k += 4) {
                float4 v = *(const float4*)(bp + k);   // conflict-free LDS.128
                acc = fmaf(v.x, v.x, acc);
                acc = fmaf(v.y, v.y, acc);
                acc = fmaf(v.z, v.z, acc);
                acc = fmaf(v.w, v.w, acc);
            }
            float r = 2.0f * (sm.fr.sqs[lane] - acc); // diagonal d2 residual
            float dist = (r > 0.f) ? sqrtf(r) : 0.f;  // where(d2>0, sqrt, 0)
            float val = 1.0f - dist;                  // MARGIN - dist
            if (val > 0.f) atomicAdd(&g_domsum[lab[crow]], val);
        }
        __syncthreads();   // chain reads of sm.fr done before smem reuse below
    } else {
        // Bucketing block: warp d compacts rows with lab==d, in row order.
        unsigned lt = (1u << lane) - 1u;
        int cnt = 0;
        for (int base = 0; base < BDIM; base += 32) {
            int l = lab[base + lane];
            unsigned m = __ballot_sync(0xffffffffu, l == w);
            if (l == w) g_idx[w][cnt + __popc(m & lt)] = base + lane;
            cnt += __popc(m);
        }
        if (lane == 0) g_cnt[w] = cnt;
        __syncthreads();
        if (threadIdx.x == 0) atom_add_release(&g_arrive1, 1u);
    }

    // ---------------- Phase B (screen blocks only) ----------------
    if (bid < NSCREEN) {
        if (threadIdx.x == 0) {
            while (ld_acquire(&g_arrive1) < (unsigned int)NBLK) __nanosleep(64);
        }
        __syncthreads();   // broadcast acquired visibility to the block

        int dom = bid & 7;
        int t   = bid >> 3;            // 0..54
        int n  = g_cnt[dom];
        int nt = (n + TILE - 1) / TILE;

        // tri id -> (ti, tj), ti >= tj
        int ti = (int)((sqrtf(8.0f * (float)t + 1.0f) - 1.0f) * 0.5f);
        while ((ti + 1) * (ti + 2) / 2 <= t) ++ti;
        while (ti * (ti + 1) / 2 > t) --ti;
        int tj = t - ti * (ti + 1) / 2;

        if (ti < nt) {   // block-uniform
            int lr = threadIdx.x >> 2;
            int q0 = threadIdx.x & 3;
            int ra = ti * TILE + lr;
            int rb = tj * TILE + lr;
            int rowA = (ra < n) ? g_idx[dom][ra] : g_idx[dom][0];
            int rowB = (rb < n) ? g_idx[dom][rb] : g_idx[dom][0];
            if (q0 == 0) {
                sm.sc.pA[lr] = (ra < n) ? g_p[rowA] : 1e30f;   // pads never survive
                sm.sc.pB[lr] = (rb < n) ? g_p[rowB] : 1e30f;
                sm.sc.iA[lr] = rowA;
                sm.sc.iB[lr] = rowB;
            }
            const float4* fa = (const float4*)(f + (size_t)rowA * DDIM);
            const float4* fb = (const float4*)(f + (size_t)rowB * DDIM);
            #pragma unroll
            for (int qq = 0; qq < 2; qq++) {
                int q = q0 + 4 * qq;
                *(float4*)&sm.sc.As[lr][q * 4] = fa[q];
                *(float4*)&sm.sc.Bs[lr][q * 4] = fb[q];
            }
            __syncthreads();

            int tx = threadIdx.x & 15;
            int ty = threadIdx.x >> 4;

            float c[4][4];
            #pragma unroll
            for (int qa = 0; qa < 4; qa++)
                #pragma unroll
                for (int qb = 0; qb < 4; qb++) c[qa][qb] = 0.f;

            #pragma unroll
            for (int kk = 0; kk < KSCR; kk += 4) {
                float4 a4[4], b4[4];
                #pragma unroll
                for (int q = 0; q < 4; q++) {
                    a4[q] = *(const float4*)&sm.sc.As[ty + 16 * q][kk];
                    b4[q] = *(const float4*)&sm.sc.Bs[tx + 16 * q][kk];
                }
                // k ascending within the float4: same per-accumulator order.
                #pragma unroll
                for (int qa = 0; qa < 4; qa++)
                    #pragma unroll
                    for (int qb = 0; qb < 4; qb++) {
                        c[qa][qb] += a4[qa].x * b4[qb].x;
                        c[qa][qb] += a4[qa].y * b4[qb].y;
                        c[qa][qb] += a4[qa].z * b4[qb].z;
                        c[qa][qb] += a4[qa].w * b4[qb].w;
                    }
            }

            // Epilogue: lower-bound test; rare survivors -> exact recheck.
            #pragma unroll
            for (int qa = 0; qa < 4; qa++) {
                int r = ty + 16 * qa;
                float pi = sm.sc.pA[r];
                #pragma unroll
                for (int qb = 0; qb < 4; qb++) {
                    int cc = tx + 16 * qb;
                    if (ti == tj && cc >= r) continue;   // strict lower triangle
                    float d2p = pi + sm.sc.pB[cc] - 2.0f * c[qa][qb];
                    if (d2p < SCREEN_THRESH) {
                        float val = pair_val_exact(f, sm.sc.iA[r], sm.sc.iB[cc]);
                        if (val > 0.f) atomicAdd(&g_domsum[dom], 2.0f * val);
                    }
                }
            }
        }
        __syncthreads();
    }

    // ---------------- Phase C: finalize ----------------
    if (threadIdx.x == 0) {
        unsigned int ticket = atom_add_release(&g_arrive2, 1u);
        if (ticket == (unsigned int)NBLK - 1u) {
            asm volatile("fence.acq_rel.gpu;" ::: "memory");
            volatile float* ds = g_domsum;
            float acc = 0.f, cnt = 0.f;
            #pragma unroll
            for (int d = 0; d < NDOM; d++) {
                int nd = g_cnt[d];
                if (nd > 1) {
                    acc += ds[d] / (float)(nd * nd);
                    cnt += 1.f;
                }
            }
            *out = (cnt > 0.f) ? (acc / cnt) : 0.f;
            // Reset state for the next graph replay (kernel boundary orders
            // these before the next launch's reads).
            #pragma unroll
            for (int d = 0; d < NDOM; d++) atomicExch(&g_domsum[d], 0.f);
            atomicExch(&g_arrive1, 0u);
            atomicExch(&g_arrive2, 0u);
        }
    }
}

extern "C" void kernel_launch(void* const* d_in, const int* in_sizes, int n_in,
                              void* d_out, int out_size) {
    const float* f   = (const float*)d_in[0];
    const int*   lab = (const int*)d_in[1];
    (void)in_sizes; (void)n_in; (void)out_size;

    fused_all_kernel<<<NBLK, 256>>>(f, lab, (float*)d_out);
}